// round 2
// baseline (speedup 1.0000x reference)
#include <cuda_runtime.h>
#include <cuda_bf16.h>
#include <math.h>

#define BS 16
#define HDIM 2048
#define QL 768
#define KVL 512
#define DR 64
#define DN 128
#define NH 16
#define NIH 8
#define IDXD 128
#define BLKSZ 128
#define BPS 32
#define MAXKV 4096
#define TOPK 1024
#define NSPLIT 8

#define T1DIM 1472   /* 768 + 512 + 64 + 128 */
#define T2DIM 4104   /* 3072 + 1024 + 8 */

#define ATT_SCALE 0.07216878364870323f   /* 1/sqrt(192) */
#define IDX_SCALE 0.08838834764831845f   /* 1/sqrt(128) */

// ---------------- scratch ----------------
__device__ float g_t1p[4][BS][T1DIM];
__device__ float g_cq[BS][QL];
__device__ float g_ckv[BS][KVL];
__device__ float g_kr[BS][DR];
__device__ float g_ki[BS][IDXD];
__device__ float g_q[BS][NH * 192];
__device__ float g_qi[BS][NIH * IDXD];
__device__ float g_hw[BS][NIH];
__device__ float g_qpe[BS][NH][DR];
__device__ float g_qlat[BS][NH][KVL];
__device__ float g_isc[BS][MAXKV];
__device__ int   g_sel[BS][TOPK];
__device__ float g_selval[BS][TOPK];
__device__ float g_m[BS][NSPLIT][NH];
__device__ float g_l[BS][NSPLIT][NH];
__device__ float g_op[BS][NSPLIT][NH][KVL];

__device__ __forceinline__ float blockSum256(float v, float* buf) {
    int tid = threadIdx.x;
    buf[tid] = v;
    __syncthreads();
    for (int s = 128; s > 0; s >>= 1) {
        if (tid < s) buf[tid] += buf[tid + s];
        __syncthreads();
    }
    float r = buf[0];
    __syncthreads();
    return r;
}

// ---------------- stage 1: x @ [w_dq | w_dkv_kr | w_idx_k] (partial over K) ----------------
// grid (6 colchunks, 4 batchgroups, 4 k-slices), 256 threads
__global__ void __launch_bounds__(256)
k_stage1(const float* __restrict__ x, const float* __restrict__ w_dq,
         const float* __restrict__ w_dkv, const float* __restrict__ w_idxk) {
    int cx = blockIdx.x, bg = blockIdx.y, z = blockIdx.z;
    int tid = threadIdx.x;
    __shared__ float s_x[4 * 512];
    int i0 = z * 512;
    for (int idx = tid; idx < 4 * 512; idx += 256) {
        int bb = idx >> 9, ii = idx & 511;
        s_x[idx] = x[(bg * 4 + bb) * HDIM + i0 + ii];
    }
    __syncthreads();
    int col = cx * 256 + tid;
    if (col >= T1DIM) return;
    const float* W; int stride, c;
    if (col < QL)                { W = w_dq;   stride = QL;       c = col; }
    else if (col < QL + KVL + DR){ W = w_dkv;  stride = KVL + DR; c = col - QL; }
    else                         { W = w_idxk; stride = IDXD;     c = col - (QL + KVL + DR); }
    const float* wp = W + (size_t)i0 * stride + c;
    float a0 = 0.f, a1 = 0.f, a2 = 0.f, a3 = 0.f;
    for (int i = 0; i < 512; i += 4) {
        float w0 = wp[(i + 0) * stride];
        float w1 = wp[(i + 1) * stride];
        float w2 = wp[(i + 2) * stride];
        float w3 = wp[(i + 3) * stride];
        float4 x0 = *(const float4*)&s_x[0 * 512 + i];
        float4 x1 = *(const float4*)&s_x[1 * 512 + i];
        float4 x2 = *(const float4*)&s_x[2 * 512 + i];
        float4 x3 = *(const float4*)&s_x[3 * 512 + i];
        a0 += x0.x * w0 + x0.y * w1 + x0.z * w2 + x0.w * w3;
        a1 += x1.x * w0 + x1.y * w1 + x1.z * w2 + x1.w * w3;
        a2 += x2.x * w0 + x2.y * w1 + x2.z * w2 + x2.w * w3;
        a3 += x3.x * w0 + x3.y * w1 + x3.z * w2 + x3.w * w3;
    }
    int b0 = bg * 4;
    g_t1p[z][b0 + 0][col] = a0;
    g_t1p[z][b0 + 1][col] = a1;
    g_t1p[z][b0 + 2][col] = a2;
    g_t1p[z][b0 + 3][col] = a3;
}

// ---------------- norm1: reduce partials, rmsnorm cq/ckv, rope kr, layernorm ki ----------------
// grid 16, 256 threads
__global__ void __launch_bounds__(256)
k_norm1(const float* __restrict__ gamma_cq, const float* __restrict__ gamma_ckv,
        const float* __restrict__ sinp, const float* __restrict__ cosp,
        const float* __restrict__ in_g, const float* __restrict__ in_b) {
    int b = blockIdx.x, tid = threadIdx.x;
    __shared__ float s_t[T1DIM];
    __shared__ float sred[256];
    for (int i = tid; i < T1DIM; i += 256) {
        s_t[i] = g_t1p[0][b][i] + g_t1p[1][b][i] + g_t1p[2][b][i] + g_t1p[3][b][i];
    }
    __syncthreads();
    // cq rmsnorm
    float ss = 0.f;
    for (int i = tid; i < QL; i += 256) ss += s_t[i] * s_t[i];
    ss = blockSum256(ss, sred);
    float r = rsqrtf(ss / (float)QL + 1e-6f);
    for (int i = tid; i < QL; i += 256) g_cq[b][i] = s_t[i] * r * gamma_cq[i];
    // ckv rmsnorm
    float s2 = 0.f;
    for (int i = tid; i < KVL; i += 256) { float v = s_t[QL + i]; s2 += v * v; }
    s2 = blockSum256(s2, sred);
    float r2 = rsqrtf(s2 / (float)KVL + 1e-6f);
    for (int i = tid; i < KVL; i += 256) g_ckv[b][i] = s_t[QL + i] * r2 * gamma_ckv[i];
    // kr rope
    if (tid < DR) {
        int d = tid;
        float v = s_t[QL + KVL + d];
        float rot = (d < 32) ? -s_t[QL + KVL + d + 32] : s_t[QL + KVL + d - 32];
        g_kr[b][d] = v * cosp[b * DR + d] + rot * sinp[b * DR + d];
    }
    // ki layernorm
    float sm = 0.f;
    for (int i = tid; i < IDXD; i += 256) sm += s_t[QL + KVL + DR + i];
    sm = blockSum256(sm, sred);
    float mean = sm / (float)IDXD;
    float sv = 0.f;
    for (int i = tid; i < IDXD; i += 256) { float c = s_t[QL + KVL + DR + i] - mean; sv += c * c; }
    sv = blockSum256(sv, sred);
    float rv = rsqrtf(sv / (float)IDXD + 1e-6f);
    for (int i = tid; i < IDXD; i += 256) {
        float c = s_t[QL + KVL + DR + i] - mean;
        g_ki[b][i] = c * rv * in_g[i] + in_b[i];
    }
}

// ---------------- stage 2: cq @ [w_uq_qr | w_idx_qb | w_idx_proj] ----------------
// grid (17 colchunks, 4 batchgroups), 256 threads
__global__ void __launch_bounds__(256)
k_stage2(const float* __restrict__ w1, const float* __restrict__ w2,
         const float* __restrict__ w3) {
    int cx = blockIdx.x, bg = blockIdx.y, tid = threadIdx.x;
    __shared__ float s_cq[4 * QL];
    for (int idx = tid; idx < 4 * QL; idx += 256)
        s_cq[idx] = g_cq[bg * 4 + idx / QL][idx % QL];
    __syncthreads();
    int col = cx * 256 + tid;
    if (col >= T2DIM) return;
    const float* W; int stride, c;
    if (col < 3072)      { W = w1; stride = 3072; c = col; }
    else if (col < 4096) { W = w2; stride = 1024; c = col - 3072; }
    else                 { W = w3; stride = 8;    c = col - 4096; }
    const float* wp = W + c;
    float a0 = 0.f, a1 = 0.f, a2 = 0.f, a3 = 0.f;
    for (int i = 0; i < QL; i += 4) {
        float w0 = wp[(i + 0) * stride];
        float w1v = wp[(i + 1) * stride];
        float w2v = wp[(i + 2) * stride];
        float w3v = wp[(i + 3) * stride];
        float4 x0 = *(const float4*)&s_cq[0 * QL + i];
        float4 x1 = *(const float4*)&s_cq[1 * QL + i];
        float4 x2 = *(const float4*)&s_cq[2 * QL + i];
        float4 x3 = *(const float4*)&s_cq[3 * QL + i];
        a0 += x0.x * w0 + x0.y * w1v + x0.z * w2v + x0.w * w3v;
        a1 += x1.x * w0 + x1.y * w1v + x1.z * w2v + x1.w * w3v;
        a2 += x2.x * w0 + x2.y * w1v + x2.z * w2v + x2.w * w3v;
        a3 += x3.x * w0 + x3.y * w1v + x3.z * w2v + x3.w * w3v;
    }
    int b0 = bg * 4;
    if (col < 3072) {
        g_q[b0 + 0][col] = a0; g_q[b0 + 1][col] = a1; g_q[b0 + 2][col] = a2; g_q[b0 + 3][col] = a3;
    } else if (col < 4096) {
        int cc = col - 3072;
        g_qi[b0 + 0][cc] = a0; g_qi[b0 + 1][cc] = a1; g_qi[b0 + 2][cc] = a2; g_qi[b0 + 3][cc] = a3;
    } else {
        int cc = col - 4096;
        g_hw[b0 + 0][cc] = a0; g_hw[b0 + 1][cc] = a1; g_hw[b0 + 2][cc] = a2; g_hw[b0 + 3][cc] = a3;
    }
}

// ---------------- q prep: rope q_pe + q_lat = q_nope @ w_uk[h] ----------------
// grid (NH, BS), 128 threads
__global__ void __launch_bounds__(128)
k_qprep(const float* __restrict__ w_uk, const float* __restrict__ sinp,
        const float* __restrict__ cosp) {
    int h = blockIdx.x, b = blockIdx.y, tid = threadIdx.x;
    __shared__ float s_qn[DN];
    s_qn[tid] = g_q[b][h * 192 + tid];
    if (tid < DR) {
        int d = tid;
        float v = g_q[b][h * 192 + DN + d];
        float rot = (d < 32) ? -g_q[b][h * 192 + DN + d + 32] : g_q[b][h * 192 + DN + d - 32];
        g_qpe[b][h][d] = v * cosp[b * DR + d] + rot * sinp[b * DR + d];
    }
    __syncthreads();
    const float* wk = w_uk + (size_t)h * DN * KVL;
    for (int c0 = 0; c0 < KVL; c0 += 128) {
        int c = c0 + tid;
        float a = 0.f;
        #pragma unroll 4
        for (int d = 0; d < DN; d++) a += s_qn[d] * wk[d * KVL + c];
        g_qlat[b][h][c] = a;
    }
}

// ---------------- index scoring ----------------
// grid (32 chunks, BS), 256 threads; warp-per-row
__global__ void __launch_bounds__(256)
k_iscore(const float* __restrict__ ikc, const int* __restrict__ bt,
         const int* __restrict__ cidx, const int* __restrict__ act_seqs) {
    int chunk = blockIdx.x, b = blockIdx.y, tid = threadIdx.x;
    __shared__ float s_qi[NIH * IDXD];
    __shared__ float s_hw[NIH];
    for (int i = tid; i < NIH * IDXD; i += 256) s_qi[i] = g_qi[b][i];
    if (tid < NIH) s_hw[tid] = g_hw[b][tid];
    __syncthreads();
    int warp = tid >> 5, lane = tid & 31;
    int act = act_seqs[b];
    int ci = cidx[b];
    for (int r = warp; r < 128; r += 8) {
        int n = chunk * 128 + r;
        if (n >= act) { if (lane == 0) g_isc[b][n] = -1e9f; continue; }
        int blk = bt[b * BPS + (n >> 7)];
        long flat = (long)blk * BLKSZ + (n & 127);
        const float* kr = (flat == (long)ci) ? g_ki[b] : ikc + flat * IDXD;
        float4 kv = *(const float4*)(kr + lane * 4);
        float acc[NIH];
        #pragma unroll
        for (int h = 0; h < NIH; h++) {
            float4 q = *(const float4*)&s_qi[h * IDXD + lane * 4];
            acc[h] = kv.x * q.x + kv.y * q.y + kv.z * q.z + kv.w * q.w;
        }
        #pragma unroll
        for (int off = 16; off; off >>= 1) {
            #pragma unroll
            for (int h = 0; h < NIH; h++)
                acc[h] += __shfl_xor_sync(0xffffffffu, acc[h], off);
        }
        if (lane == 0) {
            float s = 0.f;
            #pragma unroll
            for (int h = 0; h < NIH; h++) s += s_hw[h] * fmaxf(acc[h], 0.f);
            g_isc[b][n] = s * IDX_SCALE;
        }
    }
}

// ---------------- top-k via full bitonic sort (matches jax tie-by-index) ----------------
// grid BS, 1024 threads
__global__ void __launch_bounds__(1024)
k_topk(const int* __restrict__ act_seqs) {
    int b = blockIdx.x, tid = threadIdx.x;
    __shared__ unsigned long long keys[MAXKV];
    int act = act_seqs[b];
    for (int i = tid; i < MAXKV; i += 1024) {
        float v = (i < act) ? g_isc[b][i] : -1e9f;
        unsigned u = __float_as_uint(v);
        u = (u & 0x80000000u) ? ~u : (u | 0x80000000u);
        keys[i] = ((unsigned long long)u << 32) | (unsigned)(~(unsigned)i);
    }
    __syncthreads();
    for (int k = 2; k <= MAXKV; k <<= 1) {
        for (int j = k >> 1; j > 0; j >>= 1) {
            for (int t = tid; t < MAXKV; t += 1024) {
                int ixj = t ^ j;
                if (ixj > t) {
                    unsigned long long a = keys[t], c = keys[ixj];
                    bool up = ((t & k) == 0);
                    if ((a > c) == up) { keys[t] = c; keys[ixj] = a; }
                }
            }
            __syncthreads();
        }
    }
    if (tid < TOPK) {
        unsigned long long kk = keys[MAXKV - 1 - tid];
        int i = (int)(~(unsigned)(kk & 0xffffffffu));
        g_sel[b][tid] = i;
        g_selval[b][tid] = (i < act) ? g_isc[b][i] : -1e9f;
    }
}

// ---------------- attention partial (split-KV flash decode) ----------------
// grid (NSPLIT, BS), 512 threads
__global__ void __launch_bounds__(512)
k_attn(const float* __restrict__ kvc, const float* __restrict__ krc,
       const int* __restrict__ bt, const int* __restrict__ cidx) {
    int s = blockIdx.x, b = blockIdx.y, tid = threadIdx.x;
    __shared__ float s_qlat[NH * KVL];        // 32 KB
    __shared__ float s_qpe[NH * DR];          //  4 KB
    __shared__ float s_sc[128 * NH];          //  8 KB (scores -> p)
    __shared__ const float* s_ckvp[128];
    __shared__ const float* s_krp[128];
    __shared__ int s_vld[128];

    const float* qlb = &g_qlat[b][0][0];
    for (int i = tid; i < NH * KVL; i += 512) s_qlat[i] = qlb[i];
    const float* qpb = &g_qpe[b][0][0];
    for (int i = tid; i < NH * DR; i += 512) s_qpe[i] = qpb[i];
    if (tid < 128) {
        int j = tid;
        int n = g_sel[b][s * 128 + j];
        float v = g_selval[b][s * 128 + j];
        bool valid = v > -1e8f;
        const float* cp; const float* kp;
        if (!valid) { cp = g_ckv[b]; kp = g_kr[b]; }
        else {
            int blk = bt[b * BPS + (n >> 7)];
            long flat = (long)blk * BLKSZ + (n & 127);
            if (flat == (long)cidx[b]) { cp = g_ckv[b]; kp = g_kr[b]; }
            else { cp = kvc + flat * KVL; kp = krc + flat * DR; }
        }
        s_ckvp[j] = cp; s_krp[j] = kp; s_vld[j] = valid ? 1 : 0;
    }
    __syncthreads();

    int warp = tid >> 5, lane = tid & 31;
    // pass 1: scores
    for (int j = warp; j < 128; j += 16) {
        const float* ckv = s_ckvp[j];
        const float* krp = s_krp[j];
        float acc[NH];
        #pragma unroll
        for (int h = 0; h < NH; h++) acc[h] = 0.f;
        #pragma unroll
        for (int q = 0; q < 4; q++) {
            float4 v = *(const float4*)(ckv + 4 * (lane + 32 * q));
            #pragma unroll
            for (int h = 0; h < NH; h++) {
                float4 ql = *(const float4*)&s_qlat[h * KVL + 4 * (lane + 32 * q)];
                acc[h] += v.x * ql.x + v.y * ql.y + v.z * ql.z + v.w * ql.w;
            }
        }
        float2 kv2 = *(const float2*)(krp + 2 * lane);
        #pragma unroll
        for (int h = 0; h < NH; h++) {
            float2 qp = *(const float2*)&s_qpe[h * DR + 2 * lane];
            acc[h] += kv2.x * qp.x + kv2.y * qp.y;
        }
        #pragma unroll
        for (int off = 16; off; off >>= 1) {
            #pragma unroll
            for (int h = 0; h < NH; h++)
                acc[h] += __shfl_xor_sync(0xffffffffu, acc[h], off);
        }
        if (lane == 0) {
            bool valid = s_vld[j] != 0;
            #pragma unroll
            for (int h = 0; h < NH; h++)
                s_sc[j * NH + h] = valid ? acc[h] * ATT_SCALE : -1e9f;
        }
    }
    __syncthreads();
    // softmax partials: warp h handles head h over 128 rows
    {
        int h = warp;
        float v0 = s_sc[(lane +  0) * NH + h];
        float v1 = s_sc[(lane + 32) * NH + h];
        float v2 = s_sc[(lane + 64) * NH + h];
        float v3 = s_sc[(lane + 96) * NH + h];
        float m = fmaxf(fmaxf(v0, v1), fmaxf(v2, v3));
        #pragma unroll
        for (int off = 16; off; off >>= 1) m = fmaxf(m, __shfl_xor_sync(0xffffffffu, m, off));
        float e0 = __expf(v0 - m), e1 = __expf(v1 - m), e2 = __expf(v2 - m), e3 = __expf(v3 - m);
        s_sc[(lane +  0) * NH + h] = e0;
        s_sc[(lane + 32) * NH + h] = e1;
        s_sc[(lane + 64) * NH + h] = e2;
        s_sc[(lane + 96) * NH + h] = e3;
        float l = e0 + e1 + e2 + e3;
        #pragma unroll
        for (int off = 16; off; off >>= 1) l += __shfl_xor_sync(0xffffffffu, l, off);
        if (lane == 0) { g_m[b][s][h] = m; g_l[b][s][h] = l; }
    }
    __syncthreads();
    // pass 2: o_part[h][c] = sum_j p[j][h] * ckv[j][c], thread = c
    {
        int c = tid;
        float acc[NH];
        #pragma unroll
        for (int h = 0; h < NH; h++) acc[h] = 0.f;
        for (int j = 0; j < 128; j++) {
            float v = s_ckvp[j][c];
            float4 p0 = *(const float4*)&s_sc[j * NH + 0];
            float4 p1 = *(const float4*)&s_sc[j * NH + 4];
            float4 p2 = *(const float4*)&s_sc[j * NH + 8];
            float4 p3 = *(const float4*)&s_sc[j * NH + 12];
            acc[0]  += p0.x * v; acc[1]  += p0.y * v; acc[2]  += p0.z * v; acc[3]  += p0.w * v;
            acc[4]  += p1.x * v; acc[5]  += p1.y * v; acc[6]  += p1.z * v; acc[7]  += p1.w * v;
            acc[8]  += p2.x * v; acc[9]  += p2.y * v; acc[10] += p2.z * v; acc[11] += p2.w * v;
            acc[12] += p3.x * v; acc[13] += p3.y * v; acc[14] += p3.z * v; acc[15] += p3.w * v;
        }
        #pragma unroll
        for (int h = 0; h < NH; h++) g_op[b][s][h][c] = acc[h];
    }
}

// ---------------- combine splits + project with w_uk ----------------
// grid (NH, BS), 128 threads
__global__ void __launch_bounds__(128)
k_combine(const float* __restrict__ w_uk, float* __restrict__ out) {
    int h = blockIdx.x, b = blockIdx.y, tid = threadIdx.x;
    __shared__ float s_olat[KVL];
    __shared__ float s_w[NSPLIT];
    __shared__ float s_invl;
    if (tid == 0) {
        float M = -1e30f;
        for (int s = 0; s < NSPLIT; s++) M = fmaxf(M, g_m[b][s][h]);
        float L = 0.f;
        for (int s = 0; s < NSPLIT; s++) {
            float w = __expf(g_m[b][s][h] - M);
            s_w[s] = w;
            L += g_l[b][s][h] * w;
        }
        s_invl = 1.f / L;
    }
    __syncthreads();
    for (int c = tid; c < KVL; c += 128) {
        float a = 0.f;
        #pragma unroll
        for (int s = 0; s < NSPLIT; s++) a += g_op[b][s][h][c] * s_w[s];
        s_olat[c] = a * s_invl;
    }
    __syncthreads();
    int d = tid;
    const float* wk = w_uk + ((size_t)(h * DN + d)) * KVL;
    float a = 0.f;
    for (int c = 0; c < KVL; c += 4) {
        float4 o4 = *(const float4*)&s_olat[c];
        float4 w4 = *(const float4*)&wk[c];
        a += o4.x * w4.x + o4.y * w4.y + o4.z * w4.z + o4.w * w4.w;
    }
    out[b * (NH * DN) + h * DN + d] = a;
}

// ---------------- launch ----------------
extern "C" void kernel_launch(void* const* d_in, const int* in_sizes, int n_in,
                              void* d_out, int out_size) {
    const float* x            = (const float*)d_in[0];
    const float* w_dq         = (const float*)d_in[1];
    const float* w_uq_qr      = (const float*)d_in[2];
    const float* w_uk         = (const float*)d_in[3];
    const float* w_dkv_kr     = (const float*)d_in[4];
    const float* gamma_cq     = (const float*)d_in[5];
    const float* gamma_ckv    = (const float*)d_in[6];
    const float* sinp         = (const float*)d_in[7];
    const float* cosp         = (const float*)d_in[8];
    const int*   cache_index  = (const int*)d_in[9];
    const float* kv_cache     = (const float*)d_in[10];
    const float* kr_cache     = (const float*)d_in[11];
    const int*   block_table  = (const int*)d_in[12];
    const int*   act_seqs     = (const int*)d_in[13];
    const float* w_idx_qb     = (const float*)d_in[14];
    const float* w_idx_k      = (const float*)d_in[15];
    const float* w_idx_proj   = (const float*)d_in[16];
    const float* in_gamma_k   = (const float*)d_in[17];
    const float* in_beta_k    = (const float*)d_in[18];
    const float* index_k_cache= (const float*)d_in[19];
    float* out = (float*)d_out;

    k_stage1 <<<dim3(6, 4, 4), 256>>>(x, w_dq, w_dkv_kr, w_idx_k);
    k_norm1  <<<BS, 256>>>(gamma_cq, gamma_ckv, sinp, cosp, in_gamma_k, in_beta_k);
    k_stage2 <<<dim3(17, 4), 256>>>(w_uq_qr, w_idx_qb, w_idx_proj);
    k_qprep  <<<dim3(NH, BS), 128>>>(w_uk, sinp, cosp);
    k_iscore <<<dim3(32, BS), 256>>>(index_k_cache, block_table, cache_index, act_seqs);
    k_topk   <<<BS, 1024>>>(act_seqs);
    k_attn   <<<dim3(NSPLIT, BS), 512>>>(kv_cache, kr_cache, block_table, cache_index);
    k_combine<<<dim3(NH, BS), 128>>>(w_uk, out);
}

// round 3
// speedup vs baseline: 1.1869x; 1.1869x over previous
#include <cuda_runtime.h>
#include <cuda_bf16.h>
#include <math.h>

#define BS 16
#define HDIM 2048
#define QL 768
#define KVL 512
#define DR 64
#define DN 128
#define NH 16
#define NIH 8
#define IDXD 128
#define BLKSZ 128
#define BPS 32
#define MAXKV 4096
#define TOPK 1024
#define NSPLIT 16
#define SPLITROWS 64   /* TOPK / NSPLIT */

#define NZ 8           /* stage1 K-slices */
#define T1DIM 1472     /* 768 + 512 + 64 + 128 */
#define T2DIM 4104     /* 3072 + 1024 + 8 */

#define ATT_SCALE 0.07216878364870323f   /* 1/sqrt(192) */
#define IDX_SCALE 0.08838834764831845f   /* 1/sqrt(128) */

// ---------------- scratch ----------------
__device__ float g_t1p[NZ][BS][T1DIM];
__device__ float g_cq[BS][QL];
__device__ float g_ckv[BS][KVL];
__device__ float g_kr[BS][DR];
__device__ float g_ki[BS][IDXD];
__device__ float g_q[BS][NH * 192];
__device__ float g_qi[BS][NIH * IDXD];
__device__ float g_hw[BS][NIH];
__device__ float g_qpe[BS][NH][DR];
__device__ float g_qlat[BS][NH][KVL];
__device__ float g_isc[BS][MAXKV];
__device__ int   g_sel[BS][TOPK];
__device__ float g_selval[BS][TOPK];
__device__ float g_m[BS][NSPLIT][NH];
__device__ float g_l[BS][NSPLIT][NH];
__device__ float g_op[BS][NSPLIT][NH][KVL];

__device__ __forceinline__ float blockSum256(float v, float* buf) {
    int tid = threadIdx.x;
    buf[tid] = v;
    __syncthreads();
    for (int s = 128; s > 0; s >>= 1) {
        if (tid < s) buf[tid] += buf[tid + s];
        __syncthreads();
    }
    float r = buf[0];
    __syncthreads();
    return r;
}

// ---------------- stage 1: x @ [w_dq | w_dkv_kr | w_idx_k] (partial over K) ----------------
// grid (6 colchunks, 4 batchgroups, 8 k-slices), 256 threads
__global__ void __launch_bounds__(256)
k_stage1(const float* __restrict__ x, const float* __restrict__ w_dq,
         const float* __restrict__ w_dkv, const float* __restrict__ w_idxk) {
    int cx = blockIdx.x, bg = blockIdx.y, z = blockIdx.z;
    int tid = threadIdx.x;
    __shared__ float s_x[4 * 256];
    int i0 = z * 256;
    for (int idx = tid; idx < 4 * 256; idx += 256) {
        int bb = idx >> 8, ii = idx & 255;
        s_x[idx] = x[(bg * 4 + bb) * HDIM + i0 + ii];
    }
    __syncthreads();
    int col = cx * 256 + tid;
    if (col >= T1DIM) return;
    const float* W; int stride, c;
    if (col < QL)                { W = w_dq;   stride = QL;       c = col; }
    else if (col < QL + KVL + DR){ W = w_dkv;  stride = KVL + DR; c = col - QL; }
    else                         { W = w_idxk; stride = IDXD;     c = col - (QL + KVL + DR); }
    const float* wp = W + (size_t)i0 * stride + c;
    float a0 = 0.f, a1 = 0.f, a2 = 0.f, a3 = 0.f;
    #pragma unroll 4
    for (int i = 0; i < 256; i += 4) {
        float w0 = wp[(i + 0) * stride];
        float w1 = wp[(i + 1) * stride];
        float w2 = wp[(i + 2) * stride];
        float w3 = wp[(i + 3) * stride];
        float4 x0 = *(const float4*)&s_x[0 * 256 + i];
        float4 x1 = *(const float4*)&s_x[1 * 256 + i];
        float4 x2 = *(const float4*)&s_x[2 * 256 + i];
        float4 x3 = *(const float4*)&s_x[3 * 256 + i];
        a0 += x0.x * w0 + x0.y * w1 + x0.z * w2 + x0.w * w3;
        a1 += x1.x * w0 + x1.y * w1 + x1.z * w2 + x1.w * w3;
        a2 += x2.x * w0 + x2.y * w1 + x2.z * w2 + x2.w * w3;
        a3 += x3.x * w0 + x3.y * w1 + x3.z * w2 + x3.w * w3;
    }
    int b0 = bg * 4;
    g_t1p[z][b0 + 0][col] = a0;
    g_t1p[z][b0 + 1][col] = a1;
    g_t1p[z][b0 + 2][col] = a2;
    g_t1p[z][b0 + 3][col] = a3;
}

// ---------------- norm1: reduce partials, rmsnorm cq/ckv, rope kr, layernorm ki ----------------
// grid 16, 256 threads
__global__ void __launch_bounds__(256)
k_norm1(const float* __restrict__ gamma_cq, const float* __restrict__ gamma_ckv,
        const float* __restrict__ sinp, const float* __restrict__ cosp,
        const float* __restrict__ in_g, const float* __restrict__ in_b) {
    int b = blockIdx.x, tid = threadIdx.x;
    __shared__ float s_t[T1DIM];
    __shared__ float sred[256];
    for (int i = tid; i < T1DIM; i += 256) {
        float a = 0.f;
        #pragma unroll
        for (int z = 0; z < NZ; z++) a += g_t1p[z][b][i];
        s_t[i] = a;
    }
    __syncthreads();
    // cq rmsnorm
    float ss = 0.f;
    for (int i = tid; i < QL; i += 256) ss += s_t[i] * s_t[i];
    ss = blockSum256(ss, sred);
    float r = rsqrtf(ss / (float)QL + 1e-6f);
    for (int i = tid; i < QL; i += 256) g_cq[b][i] = s_t[i] * r * gamma_cq[i];
    // ckv rmsnorm
    float s2 = 0.f;
    for (int i = tid; i < KVL; i += 256) { float v = s_t[QL + i]; s2 += v * v; }
    s2 = blockSum256(s2, sred);
    float r2 = rsqrtf(s2 / (float)KVL + 1e-6f);
    for (int i = tid; i < KVL; i += 256) g_ckv[b][i] = s_t[QL + i] * r2 * gamma_ckv[i];
    // kr rope
    if (tid < DR) {
        int d = tid;
        float v = s_t[QL + KVL + d];
        float rot = (d < 32) ? -s_t[QL + KVL + d + 32] : s_t[QL + KVL + d - 32];
        g_kr[b][d] = v * cosp[b * DR + d] + rot * sinp[b * DR + d];
    }
    // ki layernorm
    float sm = 0.f;
    for (int i = tid; i < IDXD; i += 256) sm += s_t[QL + KVL + DR + i];
    sm = blockSum256(sm, sred);
    float mean = sm / (float)IDXD;
    float sv = 0.f;
    for (int i = tid; i < IDXD; i += 256) { float c = s_t[QL + KVL + DR + i] - mean; sv += c * c; }
    sv = blockSum256(sv, sred);
    float rv = rsqrtf(sv / (float)IDXD + 1e-6f);
    for (int i = tid; i < IDXD; i += 256) {
        float c = s_t[QL + KVL + DR + i] - mean;
        g_ki[b][i] = c * rv * in_g[i] + in_b[i];
    }
}

// ---------------- stage 2: cq @ [w_uq_qr | w_idx_qb | w_idx_proj] ----------------
// grid (17 colchunks, 8 batchgroups of 2), 256 threads
__global__ void __launch_bounds__(256)
k_stage2(const float* __restrict__ w1, const float* __restrict__ w2,
         const float* __restrict__ w3) {
    int cx = blockIdx.x, bg = blockIdx.y, tid = threadIdx.x;
    __shared__ float s_cq[2 * QL];
    for (int idx = tid; idx < 2 * QL; idx += 256)
        s_cq[idx] = g_cq[bg * 2 + idx / QL][idx % QL];
    __syncthreads();
    int col = cx * 256 + tid;
    if (col >= T2DIM) return;
    const float* W; int stride, c;
    if (col < 3072)      { W = w1; stride = 3072; c = col; }
    else if (col < 4096) { W = w2; stride = 1024; c = col - 3072; }
    else                 { W = w3; stride = 8;    c = col - 4096; }
    const float* wp = W + c;
    float a0 = 0.f, a1 = 0.f;
    #pragma unroll 4
    for (int i = 0; i < QL; i += 4) {
        float w0 = wp[(i + 0) * stride];
        float w1v = wp[(i + 1) * stride];
        float w2v = wp[(i + 2) * stride];
        float w3v = wp[(i + 3) * stride];
        float4 x0 = *(const float4*)&s_cq[0 * QL + i];
        float4 x1 = *(const float4*)&s_cq[1 * QL + i];
        a0 += x0.x * w0 + x0.y * w1v + x0.z * w2v + x0.w * w3v;
        a1 += x1.x * w0 + x1.y * w1v + x1.z * w2v + x1.w * w3v;
    }
    int b0 = bg * 2;
    if (col < 3072) {
        g_q[b0 + 0][col] = a0; g_q[b0 + 1][col] = a1;
    } else if (col < 4096) {
        int cc = col - 3072;
        g_qi[b0 + 0][cc] = a0; g_qi[b0 + 1][cc] = a1;
    } else {
        int cc = col - 4096;
        g_hw[b0 + 0][cc] = a0; g_hw[b0 + 1][cc] = a1;
    }
}

// ---------------- q prep: rope q_pe + q_lat[b][h][:] = q_nope[b][h] @ w_uk[h] ----------------
// grid (NH, 4 c-chunks), 128 threads; all 16 batches per block (w_uk read exactly once)
__global__ void __launch_bounds__(128)
k_qprep(const float* __restrict__ w_uk, const float* __restrict__ sinp,
        const float* __restrict__ cosp) {
    int h = blockIdx.x, cc = blockIdx.y, tid = threadIdx.x;
    __shared__ float s_qn[BS][DN];
    for (int idx = tid; idx < BS * DN; idx += 128) {
        int b = idx >> 7, d = idx & 127;
        s_qn[b][d] = g_q[b][h * 192 + d];
    }
    if (cc == 0) {
        for (int idx = tid; idx < BS * DR; idx += 128) {
            int b = idx >> 6, d = idx & 63;
            float v = g_q[b][h * 192 + DN + d];
            float rot = (d < 32) ? -g_q[b][h * 192 + DN + d + 32] : g_q[b][h * 192 + DN + d - 32];
            g_qpe[b][h][d] = v * cosp[b * DR + d] + rot * sinp[b * DR + d];
        }
    }
    __syncthreads();
    int c = cc * 128 + tid;
    const float* wk = w_uk + (size_t)h * DN * KVL + c;
    float acc[BS];
    #pragma unroll
    for (int b = 0; b < BS; b++) acc[b] = 0.f;
    #pragma unroll 4
    for (int d = 0; d < DN; d++) {
        float w = wk[(size_t)d * KVL];
        #pragma unroll
        for (int b = 0; b < BS; b++) acc[b] += s_qn[b][d] * w;
    }
    #pragma unroll
    for (int b = 0; b < BS; b++) g_qlat[b][h][c] = acc[b];
}

// ---------------- index scoring ----------------
// grid (32 chunks, BS), 256 threads; warp-per-row
__global__ void __launch_bounds__(256)
k_iscore(const float* __restrict__ ikc, const int* __restrict__ bt,
         const int* __restrict__ cidx, const int* __restrict__ act_seqs) {
    int chunk = blockIdx.x, b = blockIdx.y, tid = threadIdx.x;
    __shared__ float s_qi[NIH * IDXD];
    __shared__ float s_hw[NIH];
    for (int i = tid; i < NIH * IDXD; i += 256) s_qi[i] = g_qi[b][i];
    if (tid < NIH) s_hw[tid] = g_hw[b][tid];
    __syncthreads();
    int warp = tid >> 5, lane = tid & 31;
    int act = act_seqs[b];
    int ci = cidx[b];
    for (int r = warp; r < 128; r += 8) {
        int n = chunk * 128 + r;
        if (n >= act) { if (lane == 0) g_isc[b][n] = -1e9f; continue; }
        int blk = bt[b * BPS + (n >> 7)];
        long flat = (long)blk * BLKSZ + (n & 127);
        const float* kr = (flat == (long)ci) ? g_ki[b] : ikc + flat * IDXD;
        float4 kv = *(const float4*)(kr + lane * 4);
        float acc[NIH];
        #pragma unroll
        for (int h = 0; h < NIH; h++) {
            float4 q = *(const float4*)&s_qi[h * IDXD + lane * 4];
            acc[h] = kv.x * q.x + kv.y * q.y + kv.z * q.z + kv.w * q.w;
        }
        #pragma unroll
        for (int off = 16; off; off >>= 1) {
            #pragma unroll
            for (int h = 0; h < NIH; h++)
                acc[h] += __shfl_xor_sync(0xffffffffu, acc[h], off);
        }
        if (lane == 0) {
            float s = 0.f;
            #pragma unroll
            for (int h = 0; h < NIH; h++) s += s_hw[h] * fmaxf(acc[h], 0.f);
            g_isc[b][n] = s * IDX_SCALE;
        }
    }
}

// ---------------- top-k via radix threshold select (set matches jax ties-by-lowest-index) ----------------
// grid BS, 512 threads. Selection order is arbitrary — attention is permutation-invariant.
__global__ void __launch_bounds__(512)
k_topk(const int* __restrict__ act_seqs) {
    int b = blockIdx.x, tid = threadIdx.x;
    __shared__ unsigned s_key[MAXKV];         // 16 KB ordered keys
    __shared__ unsigned s_hist[256];
    __shared__ unsigned s_bm[MAXKV / 32];     // equality bitmap
    __shared__ unsigned s_cnt;
    __shared__ unsigned s_pref;               // known high bits of threshold
    __shared__ int s_rem, s_Bw, s_need;
    int act = act_seqs[b];
    for (int i = tid; i < MAXKV; i += 512) {
        float v = (i < act) ? g_isc[b][i] : -1e9f;
        unsigned u = __float_as_uint(v);
        u = (u & 0x80000000u) ? ~u : (u | 0x80000000u);
        s_key[i] = u;
    }
    if (tid == 0) { s_cnt = 0; s_rem = TOPK; s_pref = 0; }
    __syncthreads();

    // 4 radix levels (8 bits each, high->low) to find exact threshold key K
    for (int level = 0; level < 4; level++) {
        int shift = 24 - level * 8;
        if (tid < 256) s_hist[tid] = 0;
        __syncthreads();
        unsigned pref = s_pref;
        for (int i = tid; i < MAXKV; i += 512) {
            unsigned u = s_key[i];
            if (level == 0 || (u >> (shift + 8)) == pref)
                atomicAdd(&s_hist[(u >> shift) & 255u], 1u);
        }
        __syncthreads();
        if (tid == 0) {
            int r = s_rem;
            int cum = 0, bsel = 0;
            for (int xb = 255; xb >= 0; xb--) {
                int c = (int)s_hist[xb];
                if (cum + c >= r) { bsel = xb; s_rem = r - cum; break; }
                cum += c;
            }
            s_pref = (s_pref << 8) | (unsigned)bsel;
        }
        __syncthreads();
    }
    unsigned K = s_pref;   // exact threshold key; s_rem = # of ==K to take (lowest indices)

    // select all keys strictly greater than K
    for (int i = tid; i < MAXKV; i += 512) {
        if (s_key[i] > K) {
            unsigned pos = atomicAdd(&s_cnt, 1u);
            g_sel[b][pos] = i;
            g_selval[b][pos] = (i < act) ? g_isc[b][i] : -1e9f;
        }
    }
    // bitmap of ==K, then take s_rem lowest indices
    for (int w = tid; w < MAXKV / 32; w += 512) s_bm[w] = 0;
    __syncthreads();
    for (int i = tid; i < MAXKV; i += 512)
        if (s_key[i] == K) atomicOr(&s_bm[i >> 5], 1u << (i & 31));
    __syncthreads();
    if (tid == 0) {
        int need = s_rem;
        int w = 0;
        for (; w < MAXKV / 32; w++) {
            int pc = __popc(s_bm[w]);
            if (pc >= need) break;
            need -= pc;
        }
        s_Bw = w; s_need = need;
    }
    __syncthreads();
    int Bw = s_Bw, need = s_need;
    for (int i = tid; i < MAXKV; i += 512) {
        if (s_key[i] == K) {
            int w = i >> 5, bit = i & 31;
            bool take = (w < Bw) ||
                        (w == Bw && (int)__popc(s_bm[w] & ((1u << bit) - 1u)) < need);
            if (take) {
                unsigned pos = atomicAdd(&s_cnt, 1u);
                g_sel[b][pos] = i;
                g_selval[b][pos] = (i < act) ? g_isc[b][i] : -1e9f;
            }
        }
    }
}

// ---------------- attention partial (split-KV flash decode) ----------------
// grid (NSPLIT, BS), 512 threads; 64 rows per split
__global__ void __launch_bounds__(512)
k_attn(const float* __restrict__ kvc, const float* __restrict__ krc,
       const int* __restrict__ bt, const int* __restrict__ cidx) {
    int s = blockIdx.x, b = blockIdx.y, tid = threadIdx.x;
    __shared__ float s_qlat[NH * KVL];        // 32 KB
    __shared__ float s_qpe[NH * DR];          //  4 KB
    __shared__ float s_sc[SPLITROWS * NH];    //  4 KB
    __shared__ const float* s_ckvp[SPLITROWS];
    __shared__ const float* s_krp[SPLITROWS];
    __shared__ int s_vld[SPLITROWS];

    const float* qlb = &g_qlat[b][0][0];
    for (int i = tid; i < NH * KVL; i += 512) s_qlat[i] = qlb[i];
    const float* qpb = &g_qpe[b][0][0];
    for (int i = tid; i < NH * DR; i += 512) s_qpe[i] = qpb[i];
    if (tid < SPLITROWS) {
        int j = tid;
        int n = g_sel[b][s * SPLITROWS + j];
        float v = g_selval[b][s * SPLITROWS + j];
        bool valid = v > -1e8f;
        const float* cp; const float* kp;
        if (!valid) { cp = g_ckv[b]; kp = g_kr[b]; }
        else {
            int blk = bt[b * BPS + (n >> 7)];
            long flat = (long)blk * BLKSZ + (n & 127);
            if (flat == (long)cidx[b]) { cp = g_ckv[b]; kp = g_kr[b]; }
            else { cp = kvc + flat * KVL; kp = krc + flat * DR; }
        }
        s_ckvp[j] = cp; s_krp[j] = kp; s_vld[j] = valid ? 1 : 0;
    }
    __syncthreads();

    int warp = tid >> 5, lane = tid & 31;
    // pass 1: scores (each warp: 4 rows)
    for (int j = warp; j < SPLITROWS; j += 16) {
        const float* ckv = s_ckvp[j];
        const float* krp = s_krp[j];
        float acc[NH];
        #pragma unroll
        for (int h = 0; h < NH; h++) acc[h] = 0.f;
        #pragma unroll
        for (int q = 0; q < 4; q++) {
            float4 v = *(const float4*)(ckv + 4 * (lane + 32 * q));
            #pragma unroll
            for (int h = 0; h < NH; h++) {
                float4 ql = *(const float4*)&s_qlat[h * KVL + 4 * (lane + 32 * q)];
                acc[h] += v.x * ql.x + v.y * ql.y + v.z * ql.z + v.w * ql.w;
            }
        }
        float2 kv2 = *(const float2*)(krp + 2 * lane);
        #pragma unroll
        for (int h = 0; h < NH; h++) {
            float2 qp = *(const float2*)&s_qpe[h * DR + 2 * lane];
            acc[h] += kv2.x * qp.x + kv2.y * qp.y;
        }
        #pragma unroll
        for (int off = 16; off; off >>= 1) {
            #pragma unroll
            for (int h = 0; h < NH; h++)
                acc[h] += __shfl_xor_sync(0xffffffffu, acc[h], off);
        }
        if (lane == 0) {
            bool valid = s_vld[j] != 0;
            #pragma unroll
            for (int h = 0; h < NH; h++)
                s_sc[j * NH + h] = valid ? acc[h] * ATT_SCALE : -1e9f;
        }
    }
    __syncthreads();
    // softmax partials: warp h handles head h over 64 rows
    {
        int h = warp;
        float v0 = s_sc[(lane +  0) * NH + h];
        float v1 = s_sc[(lane + 32) * NH + h];
        float m = fmaxf(v0, v1);
        #pragma unroll
        for (int off = 16; off; off >>= 1) m = fmaxf(m, __shfl_xor_sync(0xffffffffu, m, off));
        float e0 = __expf(v0 - m), e1 = __expf(v1 - m);
        s_sc[(lane +  0) * NH + h] = e0;
        s_sc[(lane + 32) * NH + h] = e1;
        float l = e0 + e1;
        #pragma unroll
        for (int off = 16; off; off >>= 1) l += __shfl_xor_sync(0xffffffffu, l, off);
        if (lane == 0) { g_m[b][s][h] = m; g_l[b][s][h] = l; }
    }
    __syncthreads();
    // pass 2: o_part[h][c] = sum_j p[j][h] * ckv[j][c], thread = c, prefetched
    {
        int c = tid;
        float acc[NH];
        #pragma unroll
        for (int h = 0; h < NH; h++) acc[h] = 0.f;
        float v = s_ckvp[0][c];
        for (int j = 0; j < SPLITROWS; j++) {
            float vn = 0.f;
            if (j + 1 < SPLITROWS) vn = s_ckvp[j + 1][c];
            float4 p0 = *(const float4*)&s_sc[j * NH + 0];
            float4 p1 = *(const float4*)&s_sc[j * NH + 4];
            float4 p2 = *(const float4*)&s_sc[j * NH + 8];
            float4 p3 = *(const float4*)&s_sc[j * NH + 12];
            acc[0]  += p0.x * v; acc[1]  += p0.y * v; acc[2]  += p0.z * v; acc[3]  += p0.w * v;
            acc[4]  += p1.x * v; acc[5]  += p1.y * v; acc[6]  += p1.z * v; acc[7]  += p1.w * v;
            acc[8]  += p2.x * v; acc[9]  += p2.y * v; acc[10] += p2.z * v; acc[11] += p2.w * v;
            acc[12] += p3.x * v; acc[13] += p3.y * v; acc[14] += p3.z * v; acc[15] += p3.w * v;
            v = vn;
        }
        #pragma unroll
        for (int h = 0; h < NH; h++) g_op[b][s][h][c] = acc[h];
    }
}

// ---------------- combine splits + project with w_uk ----------------
// grid (NH, BS), 128 threads
__global__ void __launch_bounds__(128)
k_combine(const float* __restrict__ w_uk, float* __restrict__ out) {
    int h = blockIdx.x, b = blockIdx.y, tid = threadIdx.x;
    __shared__ float s_olat[KVL];
    __shared__ float s_w[NSPLIT];
    __shared__ float s_invl;
    if (tid == 0) {
        float M = -1e30f;
        for (int s = 0; s < NSPLIT; s++) M = fmaxf(M, g_m[b][s][h]);
        float L = 0.f;
        for (int s = 0; s < NSPLIT; s++) {
            float w = __expf(g_m[b][s][h] - M);
            s_w[s] = w;
            L += g_l[b][s][h] * w;
        }
        s_invl = 1.f / L;
    }
    __syncthreads();
    for (int c = tid; c < KVL; c += 128) {
        float a = 0.f;
        #pragma unroll
        for (int s = 0; s < NSPLIT; s++) a += g_op[b][s][h][c] * s_w[s];
        s_olat[c] = a * s_invl;
    }
    __syncthreads();
    int d = tid;
    const float* wk = w_uk + ((size_t)(h * DN + d)) * KVL;
    float a = 0.f;
    #pragma unroll 4
    for (int c = 0; c < KVL; c += 4) {
        float4 o4 = *(const float4*)&s_olat[c];
        float4 w4 = *(const float4*)&wk[c];
        a += o4.x * w4.x + o4.y * w4.y + o4.z * w4.z + o4.w * w4.w;
    }
    out[b * (NH * DN) + h * DN + d] = a;
}

// ---------------- launch ----------------
extern "C" void kernel_launch(void* const* d_in, const int* in_sizes, int n_in,
                              void* d_out, int out_size) {
    const float* x            = (const float*)d_in[0];
    const float* w_dq         = (const float*)d_in[1];
    const float* w_uq_qr      = (const float*)d_in[2];
    const float* w_uk         = (const float*)d_in[3];
    const float* w_dkv_kr     = (const float*)d_in[4];
    const float* gamma_cq     = (const float*)d_in[5];
    const float* gamma_ckv    = (const float*)d_in[6];
    const float* sinp         = (const float*)d_in[7];
    const float* cosp         = (const float*)d_in[8];
    const int*   cache_index  = (const int*)d_in[9];
    const float* kv_cache     = (const float*)d_in[10];
    const float* kr_cache     = (const float*)d_in[11];
    const int*   block_table  = (const int*)d_in[12];
    const int*   act_seqs     = (const int*)d_in[13];
    const float* w_idx_qb     = (const float*)d_in[14];
    const float* w_idx_k      = (const float*)d_in[15];
    const float* w_idx_proj   = (const float*)d_in[16];
    const float* in_gamma_k   = (const float*)d_in[17];
    const float* in_beta_k    = (const float*)d_in[18];
    const float* index_k_cache= (const float*)d_in[19];
    float* out = (float*)d_out;

    k_stage1 <<<dim3(6, 4, NZ), 256>>>(x, w_dq, w_dkv_kr, w_idx_k);
    k_norm1  <<<BS, 256>>>(gamma_cq, gamma_ckv, sinp, cosp, in_gamma_k, in_beta_k);
    k_stage2 <<<dim3(17, 8), 256>>>(w_uq_qr, w_idx_qb, w_idx_proj);
    k_qprep  <<<dim3(NH, 4), 128>>>(w_uk, sinp, cosp);
    k_iscore <<<dim3(32, BS), 256>>>(index_k_cache, block_table, cache_index, act_seqs);
    k_topk   <<<BS, 512>>>(act_seqs);
    k_attn   <<<dim3(NSPLIT, BS), 512>>>(kv_cache, kr_cache, block_table, cache_index);
    k_combine<<<dim3(NH, BS), 128>>>(w_uk, out);
}